// round 13
// baseline (speedup 1.0000x reference)
#include <cuda_runtime.h>
#include <math.h>

#define CM 64      // d_model
#define DI 128     // d_inner
#define DS 16      // d_state
#define NPIX 14400
#define HWD 120
#define LPIX 576
#define CLEN 144
#define NCHUNK 100   // NPIX / CLEN

// ---------------- static scratch, slotted per branch ----------------
__device__ float g_xzT[2][2*2*DI*NPIX];   // [sl][dir][256][tok]
__device__ float g_u  [2][2*DI*NPIX];
__device__ float g_dl [2][2*DI*NPIX];
__device__ float g_Bmb[2][2*NPIX*DS];
__device__ float g_Cmb[2][2*NPIX*DS];
__device__ float g_gb0[2][DI*NPIX];
__device__ float g_gb1[2][DI*NPIX];
__device__ float g_cur[2][CM*NPIX];
__device__ float g_buf[2][CM*NPIX];
__device__ float g_P  [2][2*DI*DS*NCHUNK];
__device__ float g_He [2][2*DI*DS*NCHUNK];
__device__ float g_Hsb[2][2*DI*DS*NCHUNK];
__device__ float g_nf [4*CM*NPIX];
__device__ float g_t1 [2*CM*NPIX];
__device__ float g_t2 [CM*NPIX];
__device__ float g_hub1[2*CM];
__device__ float g_hub2[CM];

__device__ __forceinline__ int pixmap(int t){
    int sq = t/LPIX, l = t%LPIX;
    int nh = l/24, nw = l%24, pi = sq/5, pj = sq%5;
    return (nh*5+pi)*HWD + (nw*5+pj);
}

// ---------------- init: cur[0]=x, cur[1]=x^T ----------------
__global__ void k_init(const float* __restrict__ x)
{
    int p = blockIdx.x*blockDim.x + threadIdx.x;
    if (p >= NPIX) return;
    int c = blockIdx.y;
    int h = p/HWD, w = p%HWD;
    g_cur[0][(size_t)c*NPIX+p] = x[(size_t)c*NPIX+p];
    g_cur[1][(size_t)c*NPIX+p] = x[(size_t)c*NPIX + w*HWD + h];
}

// ---------- fused LayerNorm + gather + in-proj GEMM, slot-batched ------------
__global__ __launch_bounds__(256) void k_inproj(const float* __restrict__ imgb,
        const float* __restrict__ in_w_all,
        const float* __restrict__ lng_all, const float* __restrict__ lnb_all,
        int stage, int pixflag)
{
    __shared__ __align__(16) float Xs[64][64];
    __shared__ float Ws[128][33];
    __shared__ float ms[64], rs[64];
    int sl = blockIdx.z;
    int i = 2*sl + stage;
    const float* img = imgb + (size_t)sl*CM*NPIX;
    const float* W   = in_w_all + (size_t)i*2*2*DI*CM;
    const float* lng = lng_all + i*CM;
    const float* lnb = lnb_all + i*CM;
    float* C = g_xzT[sl];
    int t0 = blockIdx.x*64;
    int nb = blockIdx.y*128;
    int tid = threadIdx.x;
    int tg = tid & 15, eg = tid >> 4;

#pragma unroll
    for (int r=0;r<16;r++){
        int idx = tid + r*256;
        int kk = idx>>6, tt = idx&63;
        int t = t0+tt;
        int p = pixflag ? pixmap(t) : t;
        Xs[kk][tt] = img[(size_t)kk*NPIX + p];
    }
    __syncthreads();
    if (tid < 64){
        float s = 0.f;
#pragma unroll
        for (int k=0;k<64;k++) s += Xs[k][tid];
        float m = s*(1.f/64.f), v = 0.f;
#pragma unroll
        for (int k=0;k<64;k++){ float d = Xs[k][tid]-m; v += d*d; }
        ms[tid] = m;
        rs[tid] = rsqrtf(v*(1.f/64.f) + 1e-5f);
    }
    __syncthreads();
#pragma unroll
    for (int r=0;r<16;r++){
        int idx = tid + r*256;
        int kk = idx>>6, tt = idx&63;
        Xs[kk][tt] = (Xs[kk][tt]-ms[tt])*rs[tt]*lng[kk] + lnb[kk];
    }

    float acc[8][4];
#pragma unroll
    for (int j=0;j<8;j++){ acc[j][0]=0.f; acc[j][1]=0.f; acc[j][2]=0.f; acc[j][3]=0.f; }
    for (int k0=0;k0<64;k0+=32){
        __syncthreads();
#pragma unroll
        for (int r=0;r<4;r++){
            int idx = tid + r*256;
            int e = idx>>3, kkb = (idx&7)*4;
            float4 v = *(const float4*)&W[(size_t)(nb+e)*CM + k0+kkb];
            Ws[e][kkb+0]=v.x; Ws[e][kkb+1]=v.y; Ws[e][kkb+2]=v.z; Ws[e][kkb+3]=v.w;
        }
        __syncthreads();
#pragma unroll 8
        for (int kk=0;kk<32;kk++){
            float4 xv = *(const float4*)&Xs[k0+kk][tg*4];
#pragma unroll
            for (int j=0;j<8;j++){
                float wv = Ws[eg*8+j][kk];
                acc[j][0] += xv.x*wv; acc[j][1] += xv.y*wv;
                acc[j][2] += xv.z*wv; acc[j][3] += xv.w*wv;
            }
        }
    }
#pragma unroll
    for (int j=0;j<8;j++){
        size_t row = (size_t)(nb + eg*8 + j)*NPIX;
        float4 o = make_float4(acc[j][0],acc[j][1],acc[j][2],acc[j][3]);
        *(float4*)&C[row + t0 + tg*4] = o;
    }
}

// ---- fused conv+silu + xproj GEMM + dt/softplus + B/C pack, slot-batched ----
__global__ __launch_bounds__(256) void k_cxp(
    const float* __restrict__ conv_w_all, const float* __restrict__ conv_b_all,
    const float* __restrict__ xproj_all, const float* __restrict__ dt_w_all,
    const float* __restrict__ dt_b_all, int stage, int Lseq)
{
    __shared__ __align__(16) float Us[32][64];
    __shared__ float Ws[64][33];
    __shared__ float Cs[36][65];
    __shared__ float cws[DI*4];
    __shared__ float cbs[DI];
    __shared__ float dws[4][DI];
    __shared__ float dbs[DI];
    int dir = blockIdx.y;
    int sl = blockIdx.z;
    int i = 2*sl + stage;
    int t0 = blockIdx.x*64;
    int tid = threadIdx.x;
    int tg = tid & 15, eg = tid >> 4;
    {
        const float* cw = conv_w_all + ((size_t)i*2 + dir)*DI*4;
        const float* cb = conv_b_all + ((size_t)i*2 + dir)*DI;
        const float* dw = dt_w_all + ((size_t)i*2 + dir)*DI*4;
        const float* db = dt_b_all + ((size_t)i*2 + dir)*DI;
        for (int t=tid;t<DI*4;t+=256){ cws[t]=cw[t]; dws[t&3][t>>2]=dw[t]; }
        for (int t=tid;t<DI;t+=256){ cbs[t]=cb[t]; dbs[t]=db[t]; }
    }
    const float* xb = g_xzT[sl] + (size_t)dir*2*DI*NPIX;
    float* ub = g_u[sl] + (size_t)dir*DI*NPIX;
    const float* xp = xproj_all + ((size_t)i*2 + dir)*36*DI;

    float acc[4][4];
#pragma unroll
    for (int j=0;j<4;j++){ acc[j][0]=0.f; acc[j][1]=0.f; acc[j][2]=0.f; acc[j][3]=0.f; }
    for (int k0=0;k0<DI;k0+=32){
        __syncthreads();
#pragma unroll
        for (int r=0;r<8;r++){
            int idx = tid + r*256;
            int kk = idx>>6, tt = idx&63;
            int ch = k0+kk;
            int tok = t0+tt;
            int l = tok % Lseq;
            const float* row = xb + (size_t)ch*NPIX;
            float a = cbs[ch];
            if (dir==0){
#pragma unroll
                for (int j=0;j<4;j++) if (l>=j) a += row[tok-j]*cws[ch*4+3-j];
            } else {
#pragma unroll
                for (int j=0;j<4;j++) if (l+j<Lseq) a += row[tok+j]*cws[ch*4+3-j];
            }
            float uu = a/(1.f+__expf(-a));
            Us[kk][tt] = uu;
            ub[(size_t)ch*NPIX + tok] = uu;
        }
#pragma unroll
        for (int r=0;r<2;r++){
            int idx = tid + r*256;
            int e = idx>>3, kkb = (idx&7)*4;
            float4 v = make_float4(0.f,0.f,0.f,0.f);
            if (e < 36) v = *(const float4*)&xp[(size_t)e*DI + k0+kkb];
            Ws[e][kkb+0]=v.x; Ws[e][kkb+1]=v.y; Ws[e][kkb+2]=v.z; Ws[e][kkb+3]=v.w;
        }
        __syncthreads();
#pragma unroll 8
        for (int kk=0;kk<32;kk++){
            float4 xv = *(const float4*)&Us[kk][tg*4];
#pragma unroll
            for (int j=0;j<4;j++){
                float wv = Ws[eg*4+j][kk];
                acc[j][0] += xv.x*wv; acc[j][1] += xv.y*wv;
                acc[j][2] += xv.z*wv; acc[j][3] += xv.w*wv;
            }
        }
    }
    __syncthreads();
#pragma unroll
    for (int j=0;j<4;j++){
        int n = eg*4 + j;
        if (n < 36){
#pragma unroll
            for (int mj=0;mj<4;mj++) Cs[n][tg*4+mj] = acc[j][mj];
        }
    }
    __syncthreads();
    int tokl = tid & 63;
    int kg = tid >> 6;
    int tok = t0 + tokl;
    float d0 = Cs[0][tokl], d1 = Cs[1][tokl], d2 = Cs[2][tokl], d3 = Cs[3][tokl];
    float* dlb = g_dl[sl] + (size_t)dir*DI*NPIX;
#pragma unroll 8
    for (int c=0;c<32;c++){
        int ch = kg*32 + c;
        float t = dbs[ch] + dws[0][ch]*d0 + dws[1][ch]*d1 + dws[2][ch]*d2 + dws[3][ch]*d3;
        t = (t>20.f)? t : log1pf(__expf(t));
        dlb[(size_t)ch*NPIX + tok] = t;
    }
    size_t bo = ((size_t)dir*NPIX + tok)*DS;
    if (kg < 2){
#pragma unroll
        for (int q=0;q<8;q++) g_Bmb[sl][bo + kg*8 + q] = Cs[4 + kg*8 + q][tokl];
    } else {
#pragma unroll
        for (int q=0;q<8;q++) g_Cmb[sl][bo + (kg-2)*8 + q] = Cs[20 + (kg-2)*8 + q][tokl];
    }
}

// --------- GEMM2 slot-batched --------------------------------------------
template<int TN>
__global__ __launch_bounds__(256) void k_gemm2(const float* __restrict__ X,
        const float* __restrict__ X2, const float* __restrict__ W,
        float* __restrict__ C, const float* __restrict__ base,
        const float* __restrict__ bias, const float* __restrict__ hub,
        int M, int K, int NW, int WS, int CS, int XS,
        size_t xss, size_t wss, size_t css, size_t bss,
        int rev, int mode, int xmode)
{
    constexpr int BN = 16*TN;
    __shared__ __align__(16) float Xs[32][64];
    __shared__ float Ws[BN][33];
    int sl = blockIdx.z;
    X += (size_t)sl*xss;
    if (X2) X2 += (size_t)sl*xss;
    W += (size_t)sl*wss;
    C += (size_t)sl*css;
    if (base) base += (size_t)sl*bss;
    int t0 = blockIdx.x*64;
    int wbase = blockIdx.y*WS;
    int cbase = blockIdx.y*CS;
    int xbase = blockIdx.y*XS;
    int tid = threadIdx.x;
    int tg = tid & 15, eg = tid >> 4;
    float acc[TN][4];
#pragma unroll
    for (int j=0;j<TN;j++){ acc[j][0]=0.f; acc[j][1]=0.f; acc[j][2]=0.f; acc[j][3]=0.f; }
    for (int k0=0;k0<K;k0+=32){
        if (xmode == 0){
#pragma unroll
            for (int r=0;r<2;r++){
                int i = tid + r*256;
                int kk = i>>4, tt = (i&15)*4;
                size_t gidx = (size_t)(xbase+k0+kk)*M + t0+tt;
                float4 v = *(const float4*)&X[gidx];
                if (X2){
                    float4 w = *(const float4*)&X2[gidx];
                    v.x+=w.x; v.y+=w.y; v.z+=w.z; v.w+=w.w;
                }
                *(float4*)&Xs[kk][tt] = v;
            }
        } else {
#pragma unroll
            for (int r=0;r<8;r++){
                int i = tid + r*256;
                int kk = i>>6, tt = i&63;
                int ch = k0+kk;
                int t = t0+tt;
                float v = ((t&31)==0) ? hub[ch] : X[(size_t)ch*M + t];
                Xs[kk][tt] = fmaxf(v + bias[ch], 0.f);
            }
        }
#pragma unroll
        for (int r=0;r<BN/32;r++){
            int i = tid + r*256;
            int e = i>>3, kkb = (i&7)*4;
            float4 v = make_float4(0.f,0.f,0.f,0.f);
            if (e < NW) v = *(const float4*)&W[(size_t)(wbase+e)*K + k0+kkb];
            Ws[e][kkb+0]=v.x; Ws[e][kkb+1]=v.y; Ws[e][kkb+2]=v.z; Ws[e][kkb+3]=v.w;
        }
        __syncthreads();
#pragma unroll 8
        for (int kk=0;kk<32;kk++){
            float4 xv = *(const float4*)&Xs[kk][tg*4];
#pragma unroll
            for (int j=0;j<TN;j++){
                float wv = Ws[eg*TN+j][kk];
                acc[j][0] += xv.x*wv; acc[j][1] += xv.y*wv;
                acc[j][2] += xv.z*wv; acc[j][3] += xv.w*wv;
            }
        }
        __syncthreads();
    }
#pragma unroll
    for (int j=0;j<TN;j++){
        size_t row = (size_t)(cbase + eg*TN + j)*M;
        if (mode == 0){
            if (!rev){
                float4 o = make_float4(acc[j][0],acc[j][1],acc[j][2],acc[j][3]);
                *(float4*)&C[row + t0 + tg*4] = o;
            } else {
#pragma unroll
                for (int mj=0;mj<4;mj++) C[row + (M-1-(t0+tg*4+mj))] = acc[j][mj];
            }
        } else if (mode == 1){
#pragma unroll
            for (int mj=0;mj<4;mj++){
                int p = pixmap(t0 + tg*4 + mj);
                C[row + p] = base[row + p] + acc[j][mj];
            }
        } else {
            size_t i = row + t0 + tg*4;
            float4 b = *(const float4*)&base[i];
            float4 c = *(const float4*)&C[i];
            c.x += b.x + acc[j][0]; c.y += b.y + acc[j][1];
            c.z += b.z + acc[j][2]; c.w += b.w + acc[j][3];
            *(float4*)&C[i] = c;
        }
    }
}

// --------- stage-1 window out-proj: cur+=..., nfx, nfy(rev); slot-batched ----
__global__ __launch_bounds__(256) void k_out3(const float* __restrict__ WaAll,
        const float* __restrict__ WbAll)
{
    __shared__ __align__(16) float Xs0[32][64];
    __shared__ __align__(16) float Xs1[32][64];
    __shared__ float Was[64][33];
    __shared__ float Wbs[64][33];
    int sl = blockIdx.y;
    int i = 2*sl + 1;
    const float* X0 = g_gb0[sl];
    const float* X1 = g_gb1[sl];
    const float* Wa = WaAll + (size_t)i*CM*DI;
    const float* Wb = WbAll + (size_t)i*CM*DI;
    float* cur = g_cur[sl];
    const float* buf = g_buf[sl];
    float* nfx = g_nf + (size_t)(2*sl)*CM*NPIX;
    float* nfy = g_nf + (size_t)(2*sl+1)*CM*NPIX;
    int t0 = blockIdx.x*64;
    int tid = threadIdx.x;
    int tg = tid & 15, eg = tid >> 4;
    float a1[4][4], a2[4][4], a3[4][4];
#pragma unroll
    for (int j=0;j<4;j++)
#pragma unroll
        for (int mj=0;mj<4;mj++){ a1[j][mj]=0.f; a2[j][mj]=0.f; a3[j][mj]=0.f; }
    for (int k0=0;k0<DI;k0+=32){
#pragma unroll
        for (int r=0;r<2;r++){
            int idx = tid + r*256;
            int kk = idx>>4, tt = (idx&15)*4;
            size_t gidx = (size_t)(k0+kk)*NPIX + t0+tt;
            *(float4*)&Xs0[kk][tt] = *(const float4*)&X0[gidx];
            *(float4*)&Xs1[kk][tt] = *(const float4*)&X1[gidx];
        }
#pragma unroll
        for (int r=0;r<2;r++){
            int idx = tid + r*256;
            int e = idx>>3, kkb = (idx&7)*4;
            float4 va = *(const float4*)&Wa[(size_t)e*DI + k0+kkb];
            Was[e][kkb+0]=va.x; Was[e][kkb+1]=va.y; Was[e][kkb+2]=va.z; Was[e][kkb+3]=va.w;
            float4 vb = *(const float4*)&Wb[(size_t)e*DI + k0+kkb];
            Wbs[e][kkb+0]=vb.x; Wbs[e][kkb+1]=vb.y; Wbs[e][kkb+2]=vb.z; Wbs[e][kkb+3]=vb.w;
        }
        __syncthreads();
#pragma unroll 8
        for (int kk=0;kk<32;kk++){
            float4 x0 = *(const float4*)&Xs0[kk][tg*4];
            float4 x1 = *(const float4*)&Xs1[kk][tg*4];
#pragma unroll
            for (int j=0;j<4;j++){
                float wa = Was[eg*4+j][kk];
                float wb = Wbs[eg*4+j][kk];
                a1[j][0] += x0.x*wa; a1[j][1] += x0.y*wa; a1[j][2] += x0.z*wa; a1[j][3] += x0.w*wa;
                a2[j][0] += x1.x*wa; a2[j][1] += x1.y*wa; a2[j][2] += x1.z*wa; a2[j][3] += x1.w*wa;
                a3[j][0] += x1.x*wb; a3[j][1] += x1.y*wb; a3[j][2] += x1.z*wb; a3[j][3] += x1.w*wb;
            }
        }
        __syncthreads();
    }
#pragma unroll
    for (int j=0;j<4;j++){
        size_t row = (size_t)(eg*4+j)*NPIX;
        size_t i2 = row + t0 + tg*4;
        float4 b = *(const float4*)&buf[i2];
        float4 c = *(const float4*)&cur[i2];
        c.x += b.x + a1[j][0] + a2[j][0];
        c.y += b.y + a1[j][1] + a2[j][1];
        c.z += b.z + a1[j][2] + a2[j][2];
        c.w += b.w + a1[j][3] + a2[j][3];
        *(float4*)&cur[i2] = c;
        float4 fx = make_float4(a1[j][0],a1[j][1],a1[j][2],a1[j][3]);
        *(float4*)&nfx[i2] = fx;
#pragma unroll
        for (int mj=0;mj<4;mj++) nfy[row + (NPIX-1-(t0+tg*4+mj))] = a3[j][mj];
    }
}

// ------------- unified chunked scan, 4 states/thread, time-vectorized x4 -----
// phase 1: per-chunk (P, He). grid (2, NCHUNK, 4), block 256 (64ch x 4 lanes)
__global__ void k_scan_c1(const float* __restrict__ Alog_all, int stage)
{
    int z = blockIdx.z;
    int dir = z & 1, sl = z >> 1;
    int i = 2*sl + stage;
    int chunk = blockIdx.y;
    int l4 = threadIdx.x & 3;
    int d = blockIdx.x*64 + (threadIdx.x>>2);
    size_t abase = (((size_t)i*2+dir)*DI+d)*DS + l4*4;
    float Aa0 = -__expf(Alog_all[abase+0]);
    float Aa1 = -__expf(Alog_all[abase+1]);
    float Aa2 = -__expf(Alog_all[abase+2]);
    float Aa3 = -__expf(Alog_all[abase+3]);
    const float* dlp = g_dl[sl] + ((size_t)dir*DI+d)*NPIX;
    const float* up  = g_u [sl] + ((size_t)dir*DI+d)*NPIX;
    const float* Bp  = g_Bmb[sl] + (size_t)dir*NPIX*DS;
    float h0=0.f,h1=0.f,h2=0.f,h3=0.f;
    float p0=1.f,p1=1.f,p2=1.f,p3=1.f;
    int s0 = chunk*CLEN;
    for (int tb=0; tb<CLEN; tb+=4){
        int sb = s0 + tb;
        int tokb = dir ? (NPIX-4-sb) : sb;
        float4 dd4 = *(const float4*)&dlp[tokb];
        float4 uu4 = *(const float4*)&up[tokb];
        float dds[4] = {dd4.x, dd4.y, dd4.z, dd4.w};
        float uus[4] = {uu4.x, uu4.y, uu4.z, uu4.w};
#pragma unroll
        for (int j=0;j<4;j++){
            int jj = dir ? 3-j : j;
            int tok = tokb + jj;
            float dd = dds[jj];
            float sc = dd*uus[jj];
            float4 b4 = *(const float4*)&Bp[(size_t)tok*DS + l4*4];
            float a0 = __expf(dd*Aa0), a1 = __expf(dd*Aa1);
            float a2 = __expf(dd*Aa2), a3 = __expf(dd*Aa3);
            h0 = h0*a0 + sc*b4.x; p0 *= a0;
            h1 = h1*a1 + sc*b4.y; p1 *= a1;
            h2 = h2*a2 + sc*b4.z; p2 *= a2;
            h3 = h3*a3 + sc*b4.w; p3 *= a3;
        }
    }
    size_t idx = (((size_t)dir*DI+d)*DS + l4*4)*NCHUNK + chunk;
    g_P[sl][idx+0*NCHUNK]=p0; g_He[sl][idx+0*NCHUNK]=h0;
    g_P[sl][idx+1*NCHUNK]=p1; g_He[sl][idx+1*NCHUNK]=h1;
    g_P[sl][idx+2*NCHUNK]=p2; g_He[sl][idx+2*NCHUNK]=h2;
    g_P[sl][idx+3*NCHUNK]=p3; g_He[sl][idx+3*NCHUNK]=h3;
}

// phase 2: serial inter-chunk prefix; resetP = chunks per independent seq (0 = never)
__global__ void k_scan_c2(int resetP)
{
    int idx = blockIdx.x*blockDim.x + threadIdx.x;
    if (idx >= 2*2*DI*DS) return;
    int sl = idx >> 12;
    int inner = idx & 4095;
    size_t base = (size_t)inner*NCHUNK;
    float h = 0.f;
    for (int c=0;c<NCHUNK;c++){
        if (resetP && (c % resetP) == 0) h = 0.f;
        g_Hsb[sl][base+c] = h;
        h = g_He[sl][base+c] + g_P[sl][base+c]*h;
    }
}

// phase 3: re-scan with carry-in + fused gate (time-vectorized x4)
__global__ void k_scan_c3(const float* __restrict__ Alog_all,
                          const float* __restrict__ D_all, int stage)
{
    int z = blockIdx.z;
    int dir = z & 1, sl = z >> 1;
    int i = 2*sl + stage;
    int chunk = blockIdx.y;
    int l4 = threadIdx.x & 3;
    int d = blockIdx.x*64 + (threadIdx.x>>2);
    size_t abase = (((size_t)i*2+dir)*DI+d)*DS + l4*4;
    float Aa0 = -__expf(Alog_all[abase+0]);
    float Aa1 = -__expf(Alog_all[abase+1]);
    float Aa2 = -__expf(Alog_all[abase+2]);
    float Aa3 = -__expf(Alog_all[abase+3]);
    float Dd = D_all[((size_t)i*2+dir)*DI+d];
    const float* dlp = g_dl[sl] + ((size_t)dir*DI+d)*NPIX;
    const float* up  = g_u [sl] + ((size_t)dir*DI+d)*NPIX;
    const float* Bp  = g_Bmb[sl] + (size_t)dir*NPIX*DS;
    const float* Cp  = g_Cmb[sl] + (size_t)dir*NPIX*DS;
    const float* zp  = g_xzT[sl] + (((size_t)dir*2+1)*DI+d)*NPIX;
    float* gp = (dir ? g_gb1[sl] : g_gb0[sl]) + (size_t)d*NPIX;
    size_t hidx = (((size_t)dir*DI+d)*DS + l4*4)*NCHUNK + chunk;
    float h0 = g_Hsb[sl][hidx+0*NCHUNK];
    float h1 = g_Hsb[sl][hidx+1*NCHUNK];
    float h2 = g_Hsb[sl][hidx+2*NCHUNK];
    float h3 = g_Hsb[sl][hidx+3*NCHUNK];
    int s0 = chunk*CLEN;
    for (int tb=0; tb<CLEN; tb+=4){
        int sb = s0 + tb;
        int tokb = dir ? (NPIX-4-sb) : sb;
        float4 dd4 = *(const float4*)&dlp[tokb];
        float4 uu4 = *(const float4*)&up[tokb];
        float dds[4] = {dd4.x, dd4.y, dd4.z, dd4.w};
        float uus[4] = {uu4.x, uu4.y, uu4.z, uu4.w};
        float res[4];
#pragma unroll
        for (int j=0;j<4;j++){
            int jj = dir ? 3-j : j;
            int tok = tokb + jj;
            float dd = dds[jj];
            float sc = dd*uus[jj];
            float4 b4 = *(const float4*)&Bp[(size_t)tok*DS + l4*4];
            h0 = h0*__expf(dd*Aa0) + sc*b4.x;
            h1 = h1*__expf(dd*Aa1) + sc*b4.y;
            h2 = h2*__expf(dd*Aa2) + sc*b4.z;
            h3 = h3*__expf(dd*Aa3) + sc*b4.w;
            float4 c4 = *(const float4*)&Cp[(size_t)tok*DS + l4*4];
            float cc = h0*c4.x + h1*c4.y + h2*c4.z + h3*c4.w;
            cc += __shfl_xor_sync(0xffffffffu, cc, 1);
            cc += __shfl_xor_sync(0xffffffffu, cc, 2);
            res[jj] = cc;
        }
        if (l4 == 0){
            float4 zz4 = *(const float4*)&zp[tokb];
            float zs[4] = {zz4.x, zz4.y, zz4.z, zz4.w};
            float4 o;
            o.x = (res[0] + uus[0]*Dd) * (zs[0]/(1.f+__expf(-zs[0])));
            o.y = (res[1] + uus[1]*Dd) * (zs[1]/(1.f+__expf(-zs[1])));
            o.z = (res[2] + uus[2]*Dd) * (zs[2]/(1.f+__expf(-zs[2])));
            o.w = (res[3] + uus[3]*Dd) * (zs[3]/(1.f+__expf(-zs[3])));
            *(float4*)&gp[tokb] = o;
        }
    }
}

// ---------------- GCN / final ----------------
__global__ void k_hubmean(const float* __restrict__ X, float* __restrict__ hub)
{
    int f = blockIdx.x;
    __shared__ float sm[256];
    float s = 0.f;
    for (int k=threadIdx.x;k<450;k+=256) s += X[(size_t)f*NPIX + k*32];
    sm[threadIdx.x]=s; __syncthreads();
    for (int st=128;st>0;st>>=1){
        if (threadIdx.x<st) sm[threadIdx.x]+=sm[threadIdx.x+st];
        __syncthreads();
    }
    if (threadIdx.x==0) hub[f]=sm[0]*(1.f/450.f);
}

__global__ void k_final(const float* __restrict__ x, const float* __restrict__ b2,
                        float* __restrict__ out)
{
    int p = blockIdx.x*blockDim.x + threadIdx.x;
    if (p >= NPIX) return;
    int c = blockIdx.y;
    int h = p/HWD, w = p%HWD;
    float g = ((p&31)==0 ? g_hub2[c] : g_t2[(size_t)c*NPIX+p]) + b2[c];
    out[(size_t)c*NPIX+p] = x[(size_t)c*NPIX+p] + g_cur[0][(size_t)c*NPIX+p]
        + g_cur[1][(size_t)c*NPIX + w*HWD + h] + g;
}

// ---------------- host driver ----------------
extern "C" void kernel_launch(void* const* d_in, const int* in_sizes, int n_in,
                              void* d_out, int out_size)
{
    const float* A[28];
    if (in_sizes[9] == 256){
        const int map[28] = {0,1,2,3,4,5,6,7,8, 11,12,13,14,15,16,17,18,
                             9,10, 19,20, 21,22,23,24,25,26,27};
        for (int k=0;k<28;k++) A[k]=(const float*)d_in[map[k]];
    } else {
        for (int k=0;k<28;k++) A[k]=(const float*)d_in[k];
    }
    const float* x = A[0];

    float *p_cur, *p_buf, *p_gb0, *p_gb1, *p_nf, *p_t1, *p_t2, *p_hub1, *p_hub2;
    cudaGetSymbolAddress((void**)&p_cur, g_cur);
    cudaGetSymbolAddress((void**)&p_buf, g_buf);
    cudaGetSymbolAddress((void**)&p_gb0, g_gb0);
    cudaGetSymbolAddress((void**)&p_gb1, g_gb1);
    cudaGetSymbolAddress((void**)&p_nf,  g_nf);
    cudaGetSymbolAddress((void**)&p_t1,  g_t1);
    cudaGetSymbolAddress((void**)&p_t2,  g_t2);
    cudaGetSymbolAddress((void**)&p_hub1, g_hub1);
    cudaGetSymbolAddress((void**)&p_hub2, g_hub2);

    const size_t SS = (size_t)CM*NPIX;
    const size_t GS = (size_t)DI*NPIX;
    const size_t WS2 = (size_t)2*CM*DI;

    k_init<<<dim3(113,CM),128>>>(x);

    for (int s=0; s<2; s++){
        // ---- pixel mamba; scan = chunked with reset every 4 chunks (576/144)
        k_inproj<<<dim3(225,4,2),256>>>(p_cur, A[1], A[17], A[18], s, 1);
        k_cxp<<<dim3(225,2,2),256>>>(A[2], A[3], A[4], A[5], A[6], s, LPIX);
        k_scan_c1<<<dim3(2,NCHUNK,4),256>>>(A[7], s);
        k_scan_c2<<<8,1024>>>(LPIX/CLEN);
        k_scan_c3<<<dim3(2,NCHUNK,4),256>>>(A[7], A[8], s);
        // buf = cur + pixel residual (scatter)
        k_gemm2<4><<<dim3(225,1,2),256>>>(p_gb0, p_gb1, A[21] + (size_t)s*CM*DI,
                                          p_buf, p_cur, nullptr, nullptr,
                                          NPIX, DI, 64, 64, 64, 0,
                                          GS, WS2, SS, SS, 0, 1, 0);
        // ---- window mamba; scan = chunked, no reset
        k_inproj<<<dim3(225,4,2),256>>>(p_buf, A[9], A[19], A[20], s, 0);
        k_cxp<<<dim3(225,2,2),256>>>(A[10], A[11], A[12], A[13], A[14], s, NPIX);
        k_scan_c1<<<dim3(2,NCHUNK,4),256>>>(A[15], s);
        k_scan_c2<<<8,1024>>>(0);
        k_scan_c3<<<dim3(2,NCHUNK,4),256>>>(A[15], A[16], s);
        if (s == 1){
            k_out3<<<dim3(225,2),256>>>(A[22], A[23]);
        } else {
            k_gemm2<4><<<dim3(225,1,2),256>>>(p_gb0, p_gb1, A[22] + (size_t)s*CM*DI,
                                              p_cur, p_buf, nullptr, nullptr,
                                              NPIX, DI, 64, 64, 64, 0,
                                              GS, WS2, SS, SS, 0, 2, 0);
        }
    }

    // GCN: layer 1 (256 -> 128)
    k_gemm2<8><<<dim3(225,1,1),256>>>(p_nf, nullptr, A[24], p_t1, nullptr, nullptr, nullptr,
                                      NPIX, 4*CM, 128, 128, 128, 0,
                                      0, 0, 0, 0, 0, 0, 0);
    k_hubmean<<<2*CM,256>>>(p_t1, p_hub1);
    // layer 2 (128 -> 64) with fused hub-substitute + bias + relu
    k_gemm2<4><<<dim3(225,1,1),256>>>(p_t1, nullptr, A[26], p_t2, nullptr, A[25], p_hub1,
                                      NPIX, 2*CM, 64, 64, 64, 0,
                                      0, 0, 0, 0, 0, 0, 2);
    k_hubmean<<<CM,256>>>(p_t2, p_hub2);
    k_final<<<dim3(113,CM),128>>>(x, A[27], (float*)d_out);
}

// round 14
// speedup vs baseline: 1.2245x; 1.2245x over previous
#include <cuda_runtime.h>
#include <math.h>

#define CM 64      // d_model
#define DI 128     // d_inner
#define DS 16      // d_state
#define NPIX 14400
#define HWD 120
#define LPIX 576
#define CLEN 144
#define NCHUNK 100   // NPIX / CLEN

// ---------------- static scratch, slotted per branch ----------------
__device__ float g_xzT[2][2*2*DI*NPIX];   // [sl][dir][256][tok]
__device__ float g_u  [2][2*DI*NPIX];
__device__ float g_dl [2][2*DI*NPIX];
__device__ float g_Bmb[2][2*NPIX*DS];
__device__ float g_Cmb[2][2*NPIX*DS];
__device__ float g_gb0[2][DI*NPIX];
__device__ float g_gb1[2][DI*NPIX];
__device__ float g_cur[2][CM*NPIX];
__device__ float g_buf[2][CM*NPIX];
__device__ float g_P  [2][2*DI*DS*NCHUNK];
__device__ float g_He [2][2*DI*DS*NCHUNK];
__device__ float g_Hsb[2][2*DI*DS*NCHUNK];
__device__ float g_nf [4*CM*NPIX];
__device__ float g_t1 [2*CM*NPIX];
__device__ float g_t2 [CM*NPIX];
__device__ float g_hub1[2*CM];
__device__ float g_hub2[CM];

__device__ __forceinline__ int pixmap(int t){
    int sq = t/LPIX, l = t%LPIX;
    int nh = l/24, nw = l%24, pi = sq/5, pj = sq%5;
    return (nh*5+pi)*HWD + (nw*5+pj);
}

// ---------------- init: cur[0]=x, cur[1]=x^T ----------------
__global__ void k_init(const float* __restrict__ x)
{
    int p = blockIdx.x*blockDim.x + threadIdx.x;
    if (p >= NPIX) return;
    int c = blockIdx.y;
    int h = p/HWD, w = p%HWD;
    g_cur[0][(size_t)c*NPIX+p] = x[(size_t)c*NPIX+p];
    g_cur[1][(size_t)c*NPIX+p] = x[(size_t)c*NPIX + w*HWD + h];
}

// ---------- fused LayerNorm + gather + in-proj GEMM, slot-batched ------------
__global__ __launch_bounds__(256) void k_inproj(const float* __restrict__ imgb,
        const float* __restrict__ in_w_all,
        const float* __restrict__ lng_all, const float* __restrict__ lnb_all,
        int stage, int pixflag)
{
    __shared__ __align__(16) float Xs[64][64];
    __shared__ float Ws[128][33];
    __shared__ float ms[64], rs[64];
    int sl = blockIdx.z;
    int i = 2*sl + stage;
    const float* img = imgb + (size_t)sl*CM*NPIX;
    const float* W   = in_w_all + (size_t)i*2*2*DI*CM;
    const float* lng = lng_all + i*CM;
    const float* lnb = lnb_all + i*CM;
    float* C = g_xzT[sl];
    int t0 = blockIdx.x*64;
    int nb = blockIdx.y*128;
    int tid = threadIdx.x;
    int tg = tid & 15, eg = tid >> 4;

#pragma unroll
    for (int r=0;r<16;r++){
        int idx = tid + r*256;
        int kk = idx>>6, tt = idx&63;
        int t = t0+tt;
        int p = pixflag ? pixmap(t) : t;
        Xs[kk][tt] = img[(size_t)kk*NPIX + p];
    }
    __syncthreads();
    if (tid < 64){
        float s = 0.f;
#pragma unroll
        for (int k=0;k<64;k++) s += Xs[k][tid];
        float m = s*(1.f/64.f), v = 0.f;
#pragma unroll
        for (int k=0;k<64;k++){ float d = Xs[k][tid]-m; v += d*d; }
        ms[tid] = m;
        rs[tid] = rsqrtf(v*(1.f/64.f) + 1e-5f);
    }
    __syncthreads();
#pragma unroll
    for (int r=0;r<16;r++){
        int idx = tid + r*256;
        int kk = idx>>6, tt = idx&63;
        Xs[kk][tt] = (Xs[kk][tt]-ms[tt])*rs[tt]*lng[kk] + lnb[kk];
    }

    float acc[8][4];
#pragma unroll
    for (int j=0;j<8;j++){ acc[j][0]=0.f; acc[j][1]=0.f; acc[j][2]=0.f; acc[j][3]=0.f; }
    for (int k0=0;k0<64;k0+=32){
        __syncthreads();
#pragma unroll
        for (int r=0;r<4;r++){
            int idx = tid + r*256;
            int e = idx>>3, kkb = (idx&7)*4;
            float4 v = *(const float4*)&W[(size_t)(nb+e)*CM + k0+kkb];
            Ws[e][kkb+0]=v.x; Ws[e][kkb+1]=v.y; Ws[e][kkb+2]=v.z; Ws[e][kkb+3]=v.w;
        }
        __syncthreads();
#pragma unroll 8
        for (int kk=0;kk<32;kk++){
            float4 xv = *(const float4*)&Xs[k0+kk][tg*4];
#pragma unroll
            for (int j=0;j<8;j++){
                float wv = Ws[eg*8+j][kk];
                acc[j][0] += xv.x*wv; acc[j][1] += xv.y*wv;
                acc[j][2] += xv.z*wv; acc[j][3] += xv.w*wv;
            }
        }
    }
#pragma unroll
    for (int j=0;j<8;j++){
        size_t row = (size_t)(nb + eg*8 + j)*NPIX;
        float4 o = make_float4(acc[j][0],acc[j][1],acc[j][2],acc[j][3]);
        *(float4*)&C[row + t0 + tg*4] = o;
    }
}

// ---- fused conv+silu + xproj GEMM + dt/softplus + B/C pack, slot-batched ----
__global__ __launch_bounds__(256) void k_cxp(
    const float* __restrict__ conv_w_all, const float* __restrict__ conv_b_all,
    const float* __restrict__ xproj_all, const float* __restrict__ dt_w_all,
    const float* __restrict__ dt_b_all, int stage, int Lseq)
{
    __shared__ __align__(16) float Us[32][64];
    __shared__ float Ws[64][33];
    __shared__ float Cs[36][65];
    __shared__ float cws[DI*4];
    __shared__ float cbs[DI];
    __shared__ float dws[4][DI];
    __shared__ float dbs[DI];
    int dir = blockIdx.y;
    int sl = blockIdx.z;
    int i = 2*sl + stage;
    int t0 = blockIdx.x*64;
    int tid = threadIdx.x;
    int tg = tid & 15, eg = tid >> 4;
    {
        const float* cw = conv_w_all + ((size_t)i*2 + dir)*DI*4;
        const float* cb = conv_b_all + ((size_t)i*2 + dir)*DI;
        const float* dw = dt_w_all + ((size_t)i*2 + dir)*DI*4;
        const float* db = dt_b_all + ((size_t)i*2 + dir)*DI;
        for (int t=tid;t<DI*4;t+=256){ cws[t]=cw[t]; dws[t&3][t>>2]=dw[t]; }
        for (int t=tid;t<DI;t+=256){ cbs[t]=cb[t]; dbs[t]=db[t]; }
    }
    const float* xb = g_xzT[sl] + (size_t)dir*2*DI*NPIX;
    float* ub = g_u[sl] + (size_t)dir*DI*NPIX;
    const float* xp = xproj_all + ((size_t)i*2 + dir)*36*DI;

    float acc[4][4];
#pragma unroll
    for (int j=0;j<4;j++){ acc[j][0]=0.f; acc[j][1]=0.f; acc[j][2]=0.f; acc[j][3]=0.f; }
    for (int k0=0;k0<DI;k0+=32){
        __syncthreads();
#pragma unroll
        for (int r=0;r<8;r++){
            int idx = tid + r*256;
            int kk = idx>>6, tt = idx&63;
            int ch = k0+kk;
            int tok = t0+tt;
            int l = tok % Lseq;
            const float* row = xb + (size_t)ch*NPIX;
            float a = cbs[ch];
            if (dir==0){
#pragma unroll
                for (int j=0;j<4;j++) if (l>=j) a += row[tok-j]*cws[ch*4+3-j];
            } else {
#pragma unroll
                for (int j=0;j<4;j++) if (l+j<Lseq) a += row[tok+j]*cws[ch*4+3-j];
            }
            float uu = a/(1.f+__expf(-a));
            Us[kk][tt] = uu;
            ub[(size_t)ch*NPIX + tok] = uu;
        }
#pragma unroll
        for (int r=0;r<2;r++){
            int idx = tid + r*256;
            int e = idx>>3, kkb = (idx&7)*4;
            float4 v = make_float4(0.f,0.f,0.f,0.f);
            if (e < 36) v = *(const float4*)&xp[(size_t)e*DI + k0+kkb];
            Ws[e][kkb+0]=v.x; Ws[e][kkb+1]=v.y; Ws[e][kkb+2]=v.z; Ws[e][kkb+3]=v.w;
        }
        __syncthreads();
#pragma unroll 8
        for (int kk=0;kk<32;kk++){
            float4 xv = *(const float4*)&Us[kk][tg*4];
#pragma unroll
            for (int j=0;j<4;j++){
                float wv = Ws[eg*4+j][kk];
                acc[j][0] += xv.x*wv; acc[j][1] += xv.y*wv;
                acc[j][2] += xv.z*wv; acc[j][3] += xv.w*wv;
            }
        }
    }
    __syncthreads();
#pragma unroll
    for (int j=0;j<4;j++){
        int n = eg*4 + j;
        if (n < 36){
#pragma unroll
            for (int mj=0;mj<4;mj++) Cs[n][tg*4+mj] = acc[j][mj];
        }
    }
    __syncthreads();
    int tokl = tid & 63;
    int kg = tid >> 6;
    int tok = t0 + tokl;
    float d0 = Cs[0][tokl], d1 = Cs[1][tokl], d2 = Cs[2][tokl], d3 = Cs[3][tokl];
    float* dlb = g_dl[sl] + (size_t)dir*DI*NPIX;
#pragma unroll 8
    for (int c=0;c<32;c++){
        int ch = kg*32 + c;
        float t = dbs[ch] + dws[0][ch]*d0 + dws[1][ch]*d1 + dws[2][ch]*d2 + dws[3][ch]*d3;
        t = (t>20.f)? t : log1pf(__expf(t));
        dlb[(size_t)ch*NPIX + tok] = t;
    }
    size_t bo = ((size_t)dir*NPIX + tok)*DS;
    if (kg < 2){
#pragma unroll
        for (int q=0;q<8;q++) g_Bmb[sl][bo + kg*8 + q] = Cs[4 + kg*8 + q][tokl];
    } else {
#pragma unroll
        for (int q=0;q<8;q++) g_Cmb[sl][bo + (kg-2)*8 + q] = Cs[20 + (kg-2)*8 + q][tokl];
    }
}

// --------- GEMM2 slot-batched --------------------------------------------
template<int TN>
__global__ __launch_bounds__(256) void k_gemm2(const float* __restrict__ X,
        const float* __restrict__ X2, const float* __restrict__ W,
        float* __restrict__ C, const float* __restrict__ base,
        const float* __restrict__ bias, const float* __restrict__ hub,
        int M, int K, int NW, int WS, int CS, int XS,
        size_t xss, size_t wss, size_t css, size_t bss,
        int rev, int mode, int xmode)
{
    constexpr int BN = 16*TN;
    __shared__ __align__(16) float Xs[32][64];
    __shared__ float Ws[BN][33];
    int sl = blockIdx.z;
    X += (size_t)sl*xss;
    if (X2) X2 += (size_t)sl*xss;
    W += (size_t)sl*wss;
    C += (size_t)sl*css;
    if (base) base += (size_t)sl*bss;
    int t0 = blockIdx.x*64;
    int wbase = blockIdx.y*WS;
    int cbase = blockIdx.y*CS;
    int xbase = blockIdx.y*XS;
    int tid = threadIdx.x;
    int tg = tid & 15, eg = tid >> 4;
    float acc[TN][4];
#pragma unroll
    for (int j=0;j<TN;j++){ acc[j][0]=0.f; acc[j][1]=0.f; acc[j][2]=0.f; acc[j][3]=0.f; }
    for (int k0=0;k0<K;k0+=32){
        if (xmode == 0){
#pragma unroll
            for (int r=0;r<2;r++){
                int i = tid + r*256;
                int kk = i>>4, tt = (i&15)*4;
                size_t gidx = (size_t)(xbase+k0+kk)*M + t0+tt;
                float4 v = *(const float4*)&X[gidx];
                if (X2){
                    float4 w = *(const float4*)&X2[gidx];
                    v.x+=w.x; v.y+=w.y; v.z+=w.z; v.w+=w.w;
                }
                *(float4*)&Xs[kk][tt] = v;
            }
        } else {
#pragma unroll
            for (int r=0;r<8;r++){
                int i = tid + r*256;
                int kk = i>>6, tt = i&63;
                int ch = k0+kk;
                int t = t0+tt;
                float v = ((t&31)==0) ? hub[ch] : X[(size_t)ch*M + t];
                Xs[kk][tt] = fmaxf(v + bias[ch], 0.f);
            }
        }
#pragma unroll
        for (int r=0;r<BN/32;r++){
            int i = tid + r*256;
            int e = i>>3, kkb = (i&7)*4;
            float4 v = make_float4(0.f,0.f,0.f,0.f);
            if (e < NW) v = *(const float4*)&W[(size_t)(wbase+e)*K + k0+kkb];
            Ws[e][kkb+0]=v.x; Ws[e][kkb+1]=v.y; Ws[e][kkb+2]=v.z; Ws[e][kkb+3]=v.w;
        }
        __syncthreads();
#pragma unroll 8
        for (int kk=0;kk<32;kk++){
            float4 xv = *(const float4*)&Xs[kk][tg*4];
#pragma unroll
            for (int j=0;j<TN;j++){
                float wv = Ws[eg*TN+j][kk];
                acc[j][0] += xv.x*wv; acc[j][1] += xv.y*wv;
                acc[j][2] += xv.z*wv; acc[j][3] += xv.w*wv;
            }
        }
        __syncthreads();
    }
#pragma unroll
    for (int j=0;j<TN;j++){
        size_t row = (size_t)(cbase + eg*TN + j)*M;
        if (mode == 0){
            if (!rev){
                float4 o = make_float4(acc[j][0],acc[j][1],acc[j][2],acc[j][3]);
                *(float4*)&C[row + t0 + tg*4] = o;
            } else {
#pragma unroll
                for (int mj=0;mj<4;mj++) C[row + (M-1-(t0+tg*4+mj))] = acc[j][mj];
            }
        } else if (mode == 1){
#pragma unroll
            for (int mj=0;mj<4;mj++){
                int p = pixmap(t0 + tg*4 + mj);
                C[row + p] = base[row + p] + acc[j][mj];
            }
        } else {
            size_t i = row + t0 + tg*4;
            float4 b = *(const float4*)&base[i];
            float4 c = *(const float4*)&C[i];
            c.x += b.x + acc[j][0]; c.y += b.y + acc[j][1];
            c.z += b.z + acc[j][2]; c.w += b.w + acc[j][3];
            *(float4*)&C[i] = c;
        }
    }
}

// --------- stage-1 window out-proj: cur+=..., nfx, nfy(rev); slot-batched ----
__global__ __launch_bounds__(256) void k_out3(const float* __restrict__ WaAll,
        const float* __restrict__ WbAll)
{
    __shared__ __align__(16) float Xs0[32][64];
    __shared__ __align__(16) float Xs1[32][64];
    __shared__ float Was[64][33];
    __shared__ float Wbs[64][33];
    int sl = blockIdx.y;
    int i = 2*sl + 1;
    const float* X0 = g_gb0[sl];
    const float* X1 = g_gb1[sl];
    const float* Wa = WaAll + (size_t)i*CM*DI;
    const float* Wb = WbAll + (size_t)i*CM*DI;
    float* cur = g_cur[sl];
    const float* buf = g_buf[sl];
    float* nfx = g_nf + (size_t)(2*sl)*CM*NPIX;
    float* nfy = g_nf + (size_t)(2*sl+1)*CM*NPIX;
    int t0 = blockIdx.x*64;
    int tid = threadIdx.x;
    int tg = tid & 15, eg = tid >> 4;
    float a1[4][4], a2[4][4], a3[4][4];
#pragma unroll
    for (int j=0;j<4;j++)
#pragma unroll
        for (int mj=0;mj<4;mj++){ a1[j][mj]=0.f; a2[j][mj]=0.f; a3[j][mj]=0.f; }
    for (int k0=0;k0<DI;k0+=32){
#pragma unroll
        for (int r=0;r<2;r++){
            int idx = tid + r*256;
            int kk = idx>>4, tt = (idx&15)*4;
            size_t gidx = (size_t)(k0+kk)*NPIX + t0+tt;
            *(float4*)&Xs0[kk][tt] = *(const float4*)&X0[gidx];
            *(float4*)&Xs1[kk][tt] = *(const float4*)&X1[gidx];
        }
#pragma unroll
        for (int r=0;r<2;r++){
            int idx = tid + r*256;
            int e = idx>>3, kkb = (idx&7)*4;
            float4 va = *(const float4*)&Wa[(size_t)e*DI + k0+kkb];
            Was[e][kkb+0]=va.x; Was[e][kkb+1]=va.y; Was[e][kkb+2]=va.z; Was[e][kkb+3]=va.w;
            float4 vb = *(const float4*)&Wb[(size_t)e*DI + k0+kkb];
            Wbs[e][kkb+0]=vb.x; Wbs[e][kkb+1]=vb.y; Wbs[e][kkb+2]=vb.z; Wbs[e][kkb+3]=vb.w;
        }
        __syncthreads();
#pragma unroll 8
        for (int kk=0;kk<32;kk++){
            float4 x0 = *(const float4*)&Xs0[kk][tg*4];
            float4 x1 = *(const float4*)&Xs1[kk][tg*4];
#pragma unroll
            for (int j=0;j<4;j++){
                float wa = Was[eg*4+j][kk];
                float wb = Wbs[eg*4+j][kk];
                a1[j][0] += x0.x*wa; a1[j][1] += x0.y*wa; a1[j][2] += x0.z*wa; a1[j][3] += x0.w*wa;
                a2[j][0] += x1.x*wa; a2[j][1] += x1.y*wa; a2[j][2] += x1.z*wa; a2[j][3] += x1.w*wa;
                a3[j][0] += x1.x*wb; a3[j][1] += x1.y*wb; a3[j][2] += x1.z*wb; a3[j][3] += x1.w*wb;
            }
        }
        __syncthreads();
    }
#pragma unroll
    for (int j=0;j<4;j++){
        size_t row = (size_t)(eg*4+j)*NPIX;
        size_t i2 = row + t0 + tg*4;
        float4 b = *(const float4*)&buf[i2];
        float4 c = *(const float4*)&cur[i2];
        c.x += b.x + a1[j][0] + a2[j][0];
        c.y += b.y + a1[j][1] + a2[j][1];
        c.z += b.z + a1[j][2] + a2[j][2];
        c.w += b.w + a1[j][3] + a2[j][3];
        *(float4*)&cur[i2] = c;
        float4 fx = make_float4(a1[j][0],a1[j][1],a1[j][2],a1[j][3]);
        *(float4*)&nfx[i2] = fx;
#pragma unroll
        for (int mj=0;mj<4;mj++) nfy[row + (NPIX-1-(t0+tg*4+mj))] = a3[j][mj];
    }
}

// ------------- unified chunked scan, 4 states/thread, time-vec x4 ------------
// direction specialized at compile time to keep all indices constant.
__global__ void k_scan_c1(const float* __restrict__ Alog_all, int stage)
{
    int z = blockIdx.z;
    int dir = z & 1, sl = z >> 1;
    int i = 2*sl + stage;
    int chunk = blockIdx.y;
    int l4 = threadIdx.x & 3;
    int d = blockIdx.x*64 + (threadIdx.x>>2);
    size_t abase = (((size_t)i*2+dir)*DI+d)*DS + l4*4;
    float Aa0 = -__expf(Alog_all[abase+0]);
    float Aa1 = -__expf(Alog_all[abase+1]);
    float Aa2 = -__expf(Alog_all[abase+2]);
    float Aa3 = -__expf(Alog_all[abase+3]);
    const float* dlp = g_dl[sl] + ((size_t)dir*DI+d)*NPIX;
    const float* up  = g_u [sl] + ((size_t)dir*DI+d)*NPIX;
    const float* Bp  = g_Bmb[sl] + (size_t)dir*NPIX*DS;
    float h0=0.f,h1=0.f,h2=0.f,h3=0.f;
    float p0=1.f,p1=1.f,p2=1.f,p3=1.f;
    int s0 = chunk*CLEN;

    auto step = [&](float dd, float uu, int tok){
        float sc = dd*uu;
        float4 b4 = *(const float4*)&Bp[(size_t)tok*DS + l4*4];
        float a0 = __expf(dd*Aa0), a1 = __expf(dd*Aa1);
        float a2 = __expf(dd*Aa2), a3 = __expf(dd*Aa3);
        h0 = h0*a0 + sc*b4.x; p0 *= a0;
        h1 = h1*a1 + sc*b4.y; p1 *= a1;
        h2 = h2*a2 + sc*b4.z; p2 *= a2;
        h3 = h3*a3 + sc*b4.w; p3 *= a3;
    };

    if (dir == 0){
        for (int tb=0; tb<CLEN; tb+=4){
            int tokb = s0 + tb;
            float4 dd4 = *(const float4*)&dlp[tokb];
            float4 uu4 = *(const float4*)&up[tokb];
            step(dd4.x, uu4.x, tokb+0);
            step(dd4.y, uu4.y, tokb+1);
            step(dd4.z, uu4.z, tokb+2);
            step(dd4.w, uu4.w, tokb+3);
        }
    } else {
        for (int tb=0; tb<CLEN; tb+=4){
            int tokb = NPIX-4-(s0+tb);
            float4 dd4 = *(const float4*)&dlp[tokb];
            float4 uu4 = *(const float4*)&up[tokb];
            step(dd4.w, uu4.w, tokb+3);
            step(dd4.z, uu4.z, tokb+2);
            step(dd4.y, uu4.y, tokb+1);
            step(dd4.x, uu4.x, tokb+0);
        }
    }
    size_t idx = (((size_t)dir*DI+d)*DS + l4*4)*NCHUNK + chunk;
    g_P[sl][idx+0*NCHUNK]=p0; g_He[sl][idx+0*NCHUNK]=h0;
    g_P[sl][idx+1*NCHUNK]=p1; g_He[sl][idx+1*NCHUNK]=h1;
    g_P[sl][idx+2*NCHUNK]=p2; g_He[sl][idx+2*NCHUNK]=h2;
    g_P[sl][idx+3*NCHUNK]=p3; g_He[sl][idx+3*NCHUNK]=h3;
}

// phase 2: serial inter-chunk prefix; resetP = chunks per independent seq (0 = never)
__global__ void k_scan_c2(int resetP)
{
    int idx = blockIdx.x*blockDim.x + threadIdx.x;
    if (idx >= 2*2*DI*DS) return;
    int sl = idx >> 12;
    int inner = idx & 4095;
    size_t base = (size_t)inner*NCHUNK;
    float h = 0.f;
    for (int c=0;c<NCHUNK;c++){
        if (resetP && (c % resetP) == 0) h = 0.f;
        g_Hsb[sl][base+c] = h;
        h = g_He[sl][base+c] + g_P[sl][base+c]*h;
    }
}

// phase 3: re-scan with carry-in + fused gate (time-vec x4, dir specialized)
__global__ void k_scan_c3(const float* __restrict__ Alog_all,
                          const float* __restrict__ D_all, int stage)
{
    int z = blockIdx.z;
    int dir = z & 1, sl = z >> 1;
    int i = 2*sl + stage;
    int chunk = blockIdx.y;
    int l4 = threadIdx.x & 3;
    int d = blockIdx.x*64 + (threadIdx.x>>2);
    size_t abase = (((size_t)i*2+dir)*DI+d)*DS + l4*4;
    float Aa0 = -__expf(Alog_all[abase+0]);
    float Aa1 = -__expf(Alog_all[abase+1]);
    float Aa2 = -__expf(Alog_all[abase+2]);
    float Aa3 = -__expf(Alog_all[abase+3]);
    float Dd = D_all[((size_t)i*2+dir)*DI+d];
    const float* dlp = g_dl[sl] + ((size_t)dir*DI+d)*NPIX;
    const float* up  = g_u [sl] + ((size_t)dir*DI+d)*NPIX;
    const float* Bp  = g_Bmb[sl] + (size_t)dir*NPIX*DS;
    const float* Cp  = g_Cmb[sl] + (size_t)dir*NPIX*DS;
    const float* zp  = g_xzT[sl] + (((size_t)dir*2+1)*DI+d)*NPIX;
    float* gp = (dir ? g_gb1[sl] : g_gb0[sl]) + (size_t)d*NPIX;
    size_t hidx = (((size_t)dir*DI+d)*DS + l4*4)*NCHUNK + chunk;
    float h0 = g_Hsb[sl][hidx+0*NCHUNK];
    float h1 = g_Hsb[sl][hidx+1*NCHUNK];
    float h2 = g_Hsb[sl][hidx+2*NCHUNK];
    float h3 = g_Hsb[sl][hidx+3*NCHUNK];
    int s0 = chunk*CLEN;

    auto step = [&](float dd, float uu, int tok) -> float {
        float sc = dd*uu;
        float4 b4 = *(const float4*)&Bp[(size_t)tok*DS + l4*4];
        h0 = h0*__expf(dd*Aa0) + sc*b4.x;
        h1 = h1*__expf(dd*Aa1) + sc*b4.y;
        h2 = h2*__expf(dd*Aa2) + sc*b4.z;
        h3 = h3*__expf(dd*Aa3) + sc*b4.w;
        float4 c4 = *(const float4*)&Cp[(size_t)tok*DS + l4*4];
        float cc = h0*c4.x + h1*c4.y + h2*c4.z + h3*c4.w;
        cc += __shfl_xor_sync(0xffffffffu, cc, 1);
        cc += __shfl_xor_sync(0xffffffffu, cc, 2);
        return cc;
    };

    if (dir == 0){
        for (int tb=0; tb<CLEN; tb+=4){
            int tokb = s0 + tb;
            float4 dd4 = *(const float4*)&dlp[tokb];
            float4 uu4 = *(const float4*)&up[tokb];
            float r0 = step(dd4.x, uu4.x, tokb+0);
            float r1 = step(dd4.y, uu4.y, tokb+1);
            float r2 = step(dd4.z, uu4.z, tokb+2);
            float r3 = step(dd4.w, uu4.w, tokb+3);
            if (l4 == 0){
                float4 zz4 = *(const float4*)&zp[tokb];
                float4 o;
                o.x = (r0 + uu4.x*Dd) * (zz4.x/(1.f+__expf(-zz4.x)));
                o.y = (r1 + uu4.y*Dd) * (zz4.y/(1.f+__expf(-zz4.y)));
                o.z = (r2 + uu4.z*Dd) * (zz4.z/(1.f+__expf(-zz4.z)));
                o.w = (r3 + uu4.w*Dd) * (zz4.w/(1.f+__expf(-zz4.w)));
                *(float4*)&gp[tokb] = o;
            }
        }
    } else {
        for (int tb=0; tb<CLEN; tb+=4){
            int tokb = NPIX-4-(s0+tb);
            float4 dd4 = *(const float4*)&dlp[tokb];
            float4 uu4 = *(const float4*)&up[tokb];
            float r3 = step(dd4.w, uu4.w, tokb+3);
            float r2 = step(dd4.z, uu4.z, tokb+2);
            float r1 = step(dd4.y, uu4.y, tokb+1);
            float r0 = step(dd4.x, uu4.x, tokb+0);
            if (l4 == 0){
                float4 zz4 = *(const float4*)&zp[tokb];
                float4 o;
                o.x = (r0 + uu4.x*Dd) * (zz4.x/(1.f+__expf(-zz4.x)));
                o.y = (r1 + uu4.y*Dd) * (zz4.y/(1.f+__expf(-zz4.y)));
                o.z = (r2 + uu4.z*Dd) * (zz4.z/(1.f+__expf(-zz4.z)));
                o.w = (r3 + uu4.w*Dd) * (zz4.w/(1.f+__expf(-zz4.w)));
                *(float4*)&gp[tokb] = o;
            }
        }
    }
}

// ---------------- GCN / final ----------------
__global__ void k_hubmean(const float* __restrict__ X, float* __restrict__ hub)
{
    int f = blockIdx.x;
    __shared__ float sm[256];
    float s = 0.f;
    for (int k=threadIdx.x;k<450;k+=256) s += X[(size_t)f*NPIX + k*32];
    sm[threadIdx.x]=s; __syncthreads();
    for (int st=128;st>0;st>>=1){
        if (threadIdx.x<st) sm[threadIdx.x]+=sm[threadIdx.x+st];
        __syncthreads();
    }
    if (threadIdx.x==0) hub[f]=sm[0]*(1.f/450.f);
}

__global__ void k_final(const float* __restrict__ x, const float* __restrict__ b2,
                        float* __restrict__ out)
{
    int p = blockIdx.x*blockDim.x + threadIdx.x;
    if (p >= NPIX) return;
    int c = blockIdx.y;
    int h = p/HWD, w = p%HWD;
    float g = ((p&31)==0 ? g_hub2[c] : g_t2[(size_t)c*NPIX+p]) + b2[c];
    out[(size_t)c*NPIX+p] = x[(size_t)c*NPIX+p] + g_cur[0][(size_t)c*NPIX+p]
        + g_cur[1][(size_t)c*NPIX + w*HWD + h] + g;
}

// ---------------- host driver ----------------
extern "C" void kernel_launch(void* const* d_in, const int* in_sizes, int n_in,
                              void* d_out, int out_size)
{
    const float* A[28];
    if (in_sizes[9] == 256){
        const int map[28] = {0,1,2,3,4,5,6,7,8, 11,12,13,14,15,16,17,18,
                             9,10, 19,20, 21,22,23,24,25,26,27};
        for (int k=0;k<28;k++) A[k]=(const float*)d_in[map[k]];
    } else {
        for (int k=0;k<28;k++) A[k]=(const float*)d_in[k];
    }
    const float* x = A[0];

    float *p_cur, *p_buf, *p_gb0, *p_gb1, *p_nf, *p_t1, *p_t2, *p_hub1, *p_hub2;
    cudaGetSymbolAddress((void**)&p_cur, g_cur);
    cudaGetSymbolAddress((void**)&p_buf, g_buf);
    cudaGetSymbolAddress((void**)&p_gb0, g_gb0);
    cudaGetSymbolAddress((void**)&p_gb1, g_gb1);
    cudaGetSymbolAddress((void**)&p_nf,  g_nf);
    cudaGetSymbolAddress((void**)&p_t1,  g_t1);
    cudaGetSymbolAddress((void**)&p_t2,  g_t2);
    cudaGetSymbolAddress((void**)&p_hub1, g_hub1);
    cudaGetSymbolAddress((void**)&p_hub2, g_hub2);

    const size_t SS = (size_t)CM*NPIX;
    const size_t GS = (size_t)DI*NPIX;
    const size_t WS2 = (size_t)2*CM*DI;

    k_init<<<dim3(113,CM),128>>>(x);

    for (int s=0; s<2; s++){
        // ---- pixel mamba; scan = chunked with reset every 4 chunks (576/144)
        k_inproj<<<dim3(225,4,2),256>>>(p_cur, A[1], A[17], A[18], s, 1);
        k_cxp<<<dim3(225,2,2),256>>>(A[2], A[3], A[4], A[5], A[6], s, LPIX);
        k_scan_c1<<<dim3(2,NCHUNK,4),256>>>(A[7], s);
        k_scan_c2<<<8,1024>>>(LPIX/CLEN);
        k_scan_c3<<<dim3(2,NCHUNK,4),256>>>(A[7], A[8], s);
        // buf = cur + pixel residual (scatter)
        k_gemm2<4><<<dim3(225,1,2),256>>>(p_gb0, p_gb1, A[21] + (size_t)s*CM*DI,
                                          p_buf, p_cur, nullptr, nullptr,
                                          NPIX, DI, 64, 64, 64, 0,
                                          GS, WS2, SS, SS, 0, 1, 0);
        // ---- window mamba; scan = chunked, no reset
        k_inproj<<<dim3(225,4,2),256>>>(p_buf, A[9], A[19], A[20], s, 0);
        k_cxp<<<dim3(225,2,2),256>>>(A[10], A[11], A[12], A[13], A[14], s, NPIX);
        k_scan_c1<<<dim3(2,NCHUNK,4),256>>>(A[15], s);
        k_scan_c2<<<8,1024>>>(0);
        k_scan_c3<<<dim3(2,NCHUNK,4),256>>>(A[15], A[16], s);
        if (s == 1){
            k_out3<<<dim3(225,2),256>>>(A[22], A[23]);
        } else {
            k_gemm2<4><<<dim3(225,1,2),256>>>(p_gb0, p_gb1, A[22] + (size_t)s*CM*DI,
                                              p_cur, p_buf, nullptr, nullptr,
                                              NPIX, DI, 64, 64, 64, 0,
                                              GS, WS2, SS, SS, 0, 2, 0);
        }
    }

    // GCN: layer 1 (256 -> 128)
    k_gemm2<8><<<dim3(225,1,1),256>>>(p_nf, nullptr, A[24], p_t1, nullptr, nullptr, nullptr,
                                      NPIX, 4*CM, 128, 128, 128, 0,
                                      0, 0, 0, 0, 0, 0, 0);
    k_hubmean<<<2*CM,256>>>(p_t1, p_hub1);
    // layer 2 (128 -> 64) with fused hub-substitute + bias + relu
    k_gemm2<4><<<dim3(225,1,1),256>>>(p_t1, nullptr, A[26], p_t2, nullptr, A[25], p_hub1,
                                      NPIX, 2*CM, 64, 64, 64, 0,
                                      0, 0, 0, 0, 0, 0, 2);
    k_hubmean<<<CM,256>>>(p_t2, p_hub2);
    k_final<<<dim3(113,CM),128>>>(x, A[27], (float*)d_out);
}